// round 5
// baseline (speedup 1.0000x reference)
#include <cuda_runtime.h>
#include <math.h>

// Problem constants
#define D_DIM 1024
#define S_LEN 2048
#define NB    2
#define NH    16
#define HD    64
#define NTOK  4096            // B*S
// -ln(10000)*2/64
#define NEG_LOG_BASE_OVER_32 (-0.28782313662425572f)

// ---------------- device scratch (allocation-free rule: __device__ globals) ----
__device__ float g_xn[NTOK * D_DIM];                 // layernorm(x)
__device__ float g_q[NB * NH * S_LEN * HD];          // [b,h,s,hd]
__device__ float g_k[NB * NH * S_LEN * HD];
__device__ float g_v[NB * NH * S_LEN * HD];
__device__ float g_attn[NTOK * D_DIM];               // [b,s,h,hd] token-major

// ======================= 1) LayerNorm over D=1024 ==========================
__global__ __launch_bounds__(256) void ln_kernel(const float* __restrict__ x,
                                                 const float* __restrict__ scale,
                                                 const float* __restrict__ bias) {
    int t = threadIdx.x;
    const float* xr = x + (size_t)blockIdx.x * D_DIM;
    float v[4];
    float s = 0.f, ss = 0.f;
#pragma unroll
    for (int i = 0; i < 4; i++) { v[i] = xr[t + i * 256]; s += v[i]; ss += v[i] * v[i]; }
#pragma unroll
    for (int off = 16; off; off >>= 1) {
        s  += __shfl_xor_sync(0xffffffffu, s,  off);
        ss += __shfl_xor_sync(0xffffffffu, ss, off);
    }
    __shared__ float sm[8], sm2[8];
    int w = t >> 5;
    if ((t & 31) == 0) { sm[w] = s; sm2[w] = ss; }
    __syncthreads();
    if (t < 32) {
        float a = (t < 8) ? sm[t]  : 0.f;
        float b = (t < 8) ? sm2[t] : 0.f;
#pragma unroll
        for (int off = 4; off; off >>= 1) {
            a += __shfl_xor_sync(0xffffffffu, a, off);
            b += __shfl_xor_sync(0xffffffffu, b, off);
        }
        if (t == 0) { sm[0] = a; sm2[0] = b; }
    }
    __syncthreads();
    float mu   = sm[0]  * (1.f / 1024.f);
    float var  = sm2[0] * (1.f / 1024.f) - mu * mu;
    float rstd = rsqrtf(var + 1e-6f);
    float* o = g_xn + (size_t)blockIdx.x * D_DIM;
#pragma unroll
    for (int i = 0; i < 4; i++) {
        int c = t + i * 256;
        o[c] = (v[i] - mu) * rstd * scale[c] + bias[c];
    }
}

// ======================= 2)/5) SGEMM 128x128x16, 8x8/thread =================
// mode 0: A=g_xn [4096,1024], B=w_qkv [1024,3072]; epilogue scatters q/k/v to
//         [b,h,s,hd] layout with bias.
// mode 1: A=g_attn [4096,1024], B=w_out [1024,1024]; epilogue writes outC+bias.
__global__ __launch_bounds__(256) void sgemm_kernel(const float* __restrict__ Bmat,
                                                    const float* __restrict__ bias,
                                                    float* __restrict__ outC,
                                                    int mode, int N) {
    __shared__ float As[16][128];
    __shared__ float Bs[16][128];
    const float* A = mode ? g_attn : g_xn;
    const int K = 1024;
    int tid = threadIdx.x;
    int ty = tid >> 4, tx = tid & 15;
    int row0 = blockIdx.y * 128, col0 = blockIdx.x * 128;

    float acc[8][8];
#pragma unroll
    for (int i = 0; i < 8; i++)
#pragma unroll
        for (int j = 0; j < 8; j++) acc[i][j] = 0.f;

    for (int kb = 0; kb < K / 16; kb++) {
        int k0 = kb * 16;
#pragma unroll
        for (int p = 0; p < 2; p++) {            // A tile: 128 rows x 16 cols (transposed store)
            int idx = tid + p * 256;
            int r = idx >> 2, c4 = (idx & 3) * 4;
            float4 f = *(const float4*)(A + (size_t)(row0 + r) * K + k0 + c4);
            As[c4 + 0][r] = f.x; As[c4 + 1][r] = f.y;
            As[c4 + 2][r] = f.z; As[c4 + 3][r] = f.w;
        }
#pragma unroll
        for (int p = 0; p < 2; p++) {            // B tile: 16 rows x 128 cols
            int idx = tid + p * 256;
            int r = idx >> 5, c4 = (idx & 31) * 4;
            *(float4*)&Bs[r][c4] = *(const float4*)(Bmat + (size_t)(k0 + r) * N + col0 + c4);
        }
        __syncthreads();
#pragma unroll
        for (int k = 0; k < 16; k++) {
            float a[8], b[8];
            *(float4*)&a[0] = *(float4*)&As[k][ty * 8];
            *(float4*)&a[4] = *(float4*)&As[k][ty * 8 + 4];
            *(float4*)&b[0] = *(float4*)&Bs[k][tx * 8];
            *(float4*)&b[4] = *(float4*)&Bs[k][tx * 8 + 4];
#pragma unroll
            for (int i = 0; i < 8; i++)
#pragma unroll
                for (int j = 0; j < 8; j++) acc[i][j] += a[i] * b[j];
        }
        __syncthreads();
    }

    if (mode) {
#pragma unroll
        for (int i = 0; i < 8; i++) {
            int row = row0 + ty * 8 + i;
            int colb = col0 + tx * 8;
#pragma unroll
            for (int j4 = 0; j4 < 8; j4 += 4) {
                float4 f;
                f.x = acc[i][j4 + 0] + bias[colb + j4 + 0];
                f.y = acc[i][j4 + 1] + bias[colb + j4 + 1];
                f.z = acc[i][j4 + 2] + bias[colb + j4 + 2];
                f.w = acc[i][j4 + 3] + bias[colb + j4 + 3];
                *(float4*)(outC + (size_t)row * N + colb + j4) = f;
            }
        }
    } else {
        int part = col0 >> 10;                   // tile is entirely within q, k, or v
        float* dst = (part == 0) ? g_q : (part == 1) ? g_k : g_v;
#pragma unroll
        for (int i = 0; i < 8; i++) {
            int row = row0 + ty * 8 + i;
            int b = row >> 11, s = row & 2047;
#pragma unroll
            for (int j4 = 0; j4 < 8; j4 += 4) {
                int col = col0 + tx * 8 + j4;
                int wd = col & 1023;
                int head = wd >> 6, hd = wd & 63;
                float4 f;
                f.x = acc[i][j4 + 0] + bias[col + 0];
                f.y = acc[i][j4 + 1] + bias[col + 1];
                f.z = acc[i][j4 + 2] + bias[col + 2];
                f.w = acc[i][j4 + 3] + bias[col + 3];
                size_t di = ((((size_t)b * NH + head) * S_LEN) + s) * HD + hd;
                *(float4*)(dst + di) = f;
            }
        }
    }
}

// ================= 3) per-head LayerNorm (scale only) + RoPE, in place ======
// One warp per (b,h,s) vector of 64; lane holds elems {lane, lane+32}.
__global__ __launch_bounds__(256) void lnrope_kernel(const float* __restrict__ q_scale,
                                                     const float* __restrict__ k_scale) {
    int gw   = (blockIdx.x * 256 + threadIdx.x) >> 5;   // 0 .. 131071
    int lane = threadIdx.x & 31;
    int sel  = gw >> 16;                                 // 0=q, 1=k (65536 each)
    int idx  = gw & 65535;                               // (b*H+h)*S + s
    float* p = (sel ? g_k : g_q) + (size_t)idx * 64;
    const float* sc = sel ? k_scale : q_scale;
    int s = idx & 2047;

    float x0 = p[lane], x1 = p[lane + 32];
    float sum = x0 + x1;
#pragma unroll
    for (int off = 16; off; off >>= 1) sum += __shfl_xor_sync(0xffffffffu, sum, off);
    float mu = sum * (1.f / 64.f);
    float d0 = x0 - mu, d1 = x1 - mu;
    float vs = d0 * d0 + d1 * d1;
#pragma unroll
    for (int off = 16; off; off >>= 1) vs += __shfl_xor_sync(0xffffffffu, vs, off);
    float rstd = rsqrtf(vs * (1.f / 64.f) + 1e-6f);
    float y0 = d0 * rstd * sc[lane];
    float y1 = d1 * rstd * sc[lane + 32];

    float inv = expf((float)lane * NEG_LOG_BASE_OVER_32);
    float ang = (float)s * inv;
    float c, sn;
    sincosf(ang, &sn, &c);                               // accurate range reduction
    p[lane]      = y0 * c - y1 * sn;                     // rotate_half: -x2 | x1
    p[lane + 32] = y1 * c + y0 * sn;
}

// ======================= 4) flash attention, 64x64 tiles ====================
// grid = (S/64 q-tiles, B*H). 256 threads, 4x4 outputs/thread.
__global__ __launch_bounds__(256) void attn_kernel() {
    __shared__ float Qt[64][64];   // [hd][qrow], pre-scaled by 1/8
    __shared__ float Kt[64][64];   // [hd][krow]; reused as P[qrow][kcol]
    __shared__ float Vs[64][64];   // [krow][hd]
    int bh = blockIdx.y;
    int qt = blockIdx.x;
    const float* qb = g_q + ((size_t)bh * S_LEN + qt * 64) * HD;
    const float* kb = g_k + (size_t)bh * S_LEN * HD;
    const float* vb = g_v + (size_t)bh * S_LEN * HD;
    int tid = threadIdx.x, ty = tid >> 4, tx = tid & 15;
    const float scl = 0.125f;                            // 1/sqrt(64), exact pow2

#pragma unroll
    for (int p = 0; p < 4; p++) {                        // load Q transposed, pre-scaled
        int idx = tid + p * 256;
        int r = idx >> 4, c4 = (idx & 15) * 4;
        float4 f = *(const float4*)(qb + r * 64 + c4);
        Qt[c4 + 0][r] = f.x * scl; Qt[c4 + 1][r] = f.y * scl;
        Qt[c4 + 2][r] = f.z * scl; Qt[c4 + 3][r] = f.w * scl;
    }

    float m[4], l[4], o[4][4];
#pragma unroll
    for (int i = 0; i < 4; i++) {
        m[i] = -1e30f; l[i] = 0.f;
#pragma unroll
        for (int j = 0; j < 4; j++) o[i][j] = 0.f;
    }

    for (int kt = 0; kt < S_LEN / 64; kt++) {
        __syncthreads();                                 // protects Qt (iter0), Ps/Vs (iter>0)
        const float* kbt = kb + kt * 64 * 64;
        const float* vbt = vb + kt * 64 * 64;
#pragma unroll
        for (int p = 0; p < 4; p++) {
            int idx = tid + p * 256;
            int r = idx >> 4, c4 = (idx & 15) * 4;
            float4 f = *(const float4*)(kbt + r * 64 + c4);
            Kt[c4 + 0][r] = f.x; Kt[c4 + 1][r] = f.y;
            Kt[c4 + 2][r] = f.z; Kt[c4 + 3][r] = f.w;
            *(float4*)&Vs[r][c4] = *(const float4*)(vbt + r * 64 + c4);
        }
        __syncthreads();

        float sv[4][4];
#pragma unroll
        for (int i = 0; i < 4; i++)
#pragma unroll
            for (int j = 0; j < 4; j++) sv[i][j] = 0.f;
#pragma unroll 16
        for (int kk = 0; kk < 64; kk++) {                // S = Q @ K^T
            float4 a = *(float4*)&Qt[kk][ty * 4];
            float4 b = *(float4*)&Kt[kk][tx * 4];
            sv[0][0] += a.x * b.x; sv[0][1] += a.x * b.y; sv[0][2] += a.x * b.z; sv[0][3] += a.x * b.w;
            sv[1][0] += a.y * b.x; sv[1][1] += a.y * b.y; sv[1][2] += a.y * b.z; sv[1][3] += a.y * b.w;
            sv[2][0] += a.z * b.x; sv[2][1] += a.z * b.y; sv[2][2] += a.z * b.z; sv[2][3] += a.z * b.w;
            sv[3][0] += a.w * b.x; sv[3][1] += a.w * b.y; sv[3][2] += a.w * b.z; sv[3][3] += a.w * b.w;
        }
        __syncthreads();                                 // Kt reads done before Ps reuse

        // online softmax; row owned by 16 threads (same ty), shfl width 16
#pragma unroll
        for (int i = 0; i < 4; i++) {
            float rm = fmaxf(fmaxf(sv[i][0], sv[i][1]), fmaxf(sv[i][2], sv[i][3]));
#pragma unroll
            for (int off = 8; off; off >>= 1)
                rm = fmaxf(rm, __shfl_xor_sync(0xffffffffu, rm, off, 16));
            float mn = fmaxf(m[i], rm);
            float alpha = __expf(m[i] - mn);
            m[i] = mn;
            float rs = 0.f;
#pragma unroll
            for (int j = 0; j < 4; j++) { sv[i][j] = __expf(sv[i][j] - mn); rs += sv[i][j]; }
#pragma unroll
            for (int off = 8; off; off >>= 1)
                rs += __shfl_xor_sync(0xffffffffu, rs, off, 16);
            l[i] = l[i] * alpha + rs;
#pragma unroll
            for (int j = 0; j < 4; j++) o[i][j] *= alpha;
        }

        float* Ps = &Kt[0][0];                           // P[qrow][kcol], stride 64
#pragma unroll
        for (int i = 0; i < 4; i++) {
            float4 f; f.x = sv[i][0]; f.y = sv[i][1]; f.z = sv[i][2]; f.w = sv[i][3];
            *(float4*)&Ps[(ty * 4 + i) * 64 + tx * 4] = f;
        }
        __syncthreads();

#pragma unroll 16
        for (int kk = 0; kk < 64; kk++) {                // O += P @ V
            float a0 = Ps[(ty * 4 + 0) * 64 + kk];
            float a1 = Ps[(ty * 4 + 1) * 64 + kk];
            float a2 = Ps[(ty * 4 + 2) * 64 + kk];
            float a3 = Ps[(ty * 4 + 3) * 64 + kk];
            float4 b = *(float4*)&Vs[kk][tx * 4];
            o[0][0] += a0 * b.x; o[0][1] += a0 * b.y; o[0][2] += a0 * b.z; o[0][3] += a0 * b.w;
            o[1][0] += a1 * b.x; o[1][1] += a1 * b.y; o[1][2] += a1 * b.z; o[1][3] += a1 * b.w;
            o[2][0] += a2 * b.x; o[2][1] += a2 * b.y; o[2][2] += a2 * b.z; o[2][3] += a2 * b.w;
            o[3][0] += a3 * b.x; o[3][1] += a3 * b.y; o[3][2] += a3 * b.z; o[3][3] += a3 * b.w;
        }
    }

    int b = bh >> 4, h = bh & 15;
#pragma unroll
    for (int i = 0; i < 4; i++) {
        float inv = 1.f / l[i];
        int srow = qt * 64 + ty * 4 + i;
        float4 f; f.x = o[i][0] * inv; f.y = o[i][1] * inv; f.z = o[i][2] * inv; f.w = o[i][3] * inv;
        *(float4*)(g_attn + (((size_t)b * S_LEN + srow) * NH + h) * HD + tx * 4) = f;
    }
}

// =========================== launch =======================================
extern "C" void kernel_launch(void* const* d_in, const int* in_sizes, int n_in,
                              void* d_out, int out_size) {
    const float* x        = (const float*)d_in[0];
    const float* w_qkv    = (const float*)d_in[1];
    const float* b_qkv    = (const float*)d_in[2];
    const float* w_out    = (const float*)d_in[3];
    const float* b_out    = (const float*)d_in[4];
    const float* ln_scale = (const float*)d_in[5];
    const float* ln_bias  = (const float*)d_in[6];
    const float* q_scale  = (const float*)d_in[7];
    const float* k_scale  = (const float*)d_in[8];
    float* out = (float*)d_out;

    ln_kernel<<<NTOK, 256>>>(x, ln_scale, ln_bias);
    sgemm_kernel<<<dim3(3 * D_DIM / 128, NTOK / 128), 256>>>(w_qkv, b_qkv, nullptr, 0, 3 * D_DIM);
    lnrope_kernel<<<2 * NB * NH * S_LEN / 8, 256>>>(q_scale, k_scale);
    attn_kernel<<<dim3(S_LEN / 64, NB * NH), 256>>>();
    sgemm_kernel<<<dim3(D_DIM / 128, NTOK / 128), 256>>>(w_out, b_out, out, 1, D_DIM);
}

// round 6
// speedup vs baseline: 3.3668x; 3.3668x over previous
#include <cuda_runtime.h>
#include <math.h>
#include <stdint.h>

// Problem constants
#define D_DIM 1024
#define S_LEN 2048
#define NB    2
#define NH    16
#define HD    64
#define NTOK  4096            // B*S
// -ln(10000)*2/64
#define NEG_LOG_BASE_OVER_32 (-0.28782313662425572f)

// ---------------- device scratch (allocation-free rule) ----------------------
__device__ float g_xn[NTOK * D_DIM];                 // layernorm(x)
__device__ float g_q[NB * NH * S_LEN * HD];          // [b,h,s,hd]
__device__ float g_k[NB * NH * S_LEN * HD];
__device__ float g_v[NB * NH * S_LEN * HD];
__device__ float g_attn[NTOK * D_DIM];               // [b,s,h,hd] token-major

// ---------------- tf32 helpers ----------------------------------------------
__device__ __forceinline__ uint32_t f2tf(float f) {
    uint32_t u;
    asm("cvt.rna.tf32.f32 %0, %1;" : "=r"(u) : "f"(f));
    return u;
}

// D = A(m16k8, row) * B(k8n8, col) + C, tf32 inputs, f32 accum
__device__ __forceinline__ void mma_tf32(float d[4], const uint32_t a[4],
                                         const uint32_t b[2], const float c[4]) {
    asm volatile(
        "mma.sync.aligned.m16n8k8.row.col.f32.tf32.tf32.f32 "
        "{%0,%1,%2,%3}, {%4,%5,%6,%7}, {%8,%9}, {%10,%11,%12,%13};"
        : "=f"(d[0]), "=f"(d[1]), "=f"(d[2]), "=f"(d[3])
        : "r"(a[0]), "r"(a[1]), "r"(a[2]), "r"(a[3]),
          "r"(b[0]), "r"(b[1]),
          "f"(c[0]), "f"(c[1]), "f"(c[2]), "f"(c[3]));
}

// ======================= 1) LayerNorm over D=1024 ============================
__global__ __launch_bounds__(256) void ln_kernel(const float* __restrict__ x,
                                                 const float* __restrict__ scale,
                                                 const float* __restrict__ bias) {
    int t = threadIdx.x;
    const float* xr = x + (size_t)blockIdx.x * D_DIM;
    float v[4];
    float s = 0.f, ss = 0.f;
#pragma unroll
    for (int i = 0; i < 4; i++) { v[i] = xr[t + i * 256]; s += v[i]; ss += v[i] * v[i]; }
#pragma unroll
    for (int off = 16; off; off >>= 1) {
        s  += __shfl_xor_sync(0xffffffffu, s,  off);
        ss += __shfl_xor_sync(0xffffffffu, ss, off);
    }
    __shared__ float sm[8], sm2[8];
    int w = t >> 5;
    if ((t & 31) == 0) { sm[w] = s; sm2[w] = ss; }
    __syncthreads();
    if (t < 32) {
        float a = (t < 8) ? sm[t]  : 0.f;
        float b = (t < 8) ? sm2[t] : 0.f;
#pragma unroll
        for (int off = 4; off; off >>= 1) {
            a += __shfl_xor_sync(0xffffffffu, a, off);
            b += __shfl_xor_sync(0xffffffffu, b, off);
        }
        if (t == 0) { sm[0] = a; sm2[0] = b; }
    }
    __syncthreads();
    float mu   = sm[0]  * (1.f / 1024.f);
    float var  = sm2[0] * (1.f / 1024.f) - mu * mu;
    float rstd = rsqrtf(var + 1e-6f);
    float* o = g_xn + (size_t)blockIdx.x * D_DIM;
#pragma unroll
    for (int i = 0; i < 4; i++) {
        int c = t + i * 256;
        o[c] = (v[i] - mu) * rstd * scale[c] + bias[c];
    }
}

// ======================= 2)/5) tf32 tensor-core GEMM =========================
// 128x128 block tile, K-block 32, 8 warps (2x4), warp tile 64x32.
// As stored [k][m] (transposed) with XOR swizzle m^((k>>2)<<2), stride 136.
// Bs stored [k][n], stride 136. Both fragment-read and staging-store
// bank-conflict-free by construction.
#define GST 136
__device__ __forceinline__ int asw(int k, int m) { return k * GST + (m ^ (((k >> 2) & 7) << 2)); }

__global__ __launch_bounds__(256) void gemm_tc(const float* __restrict__ Bmat,
                                               const float* __restrict__ bias,
                                               float* __restrict__ outC,
                                               int mode, int N) {
    __shared__ uint32_t As[32 * GST];
    __shared__ uint32_t Bs[32 * GST];
    const float* A = mode ? g_attn : g_xn;
    const int K = 1024;
    int tid = threadIdx.x;
    int lane = tid & 31, warp = tid >> 5;
    int wm = warp >> 2, wn = warp & 3;
    int g = lane >> 2, tq = lane & 3;
    int row0 = blockIdx.y * 128, col0 = blockIdx.x * 128;

    float acc[4][4][4];
#pragma unroll
    for (int i = 0; i < 4; i++)
#pragma unroll
        for (int j = 0; j < 4; j++)
#pragma unroll
            for (int r = 0; r < 4; r++) acc[i][j][r] = 0.f;

    for (int kb = 0; kb < K / 32; kb++) {
        int k0 = kb * 32;
        // stage A: 128 rows x 32 k, transposed+swizzled
#pragma unroll
        for (int p = 0; p < 4; p++) {
            int idx = tid + p * 256;
            int r = idx >> 3, c4 = (idx & 7) * 4;
            float4 f = *(const float4*)(A + (size_t)(row0 + r) * K + k0 + c4);
            As[asw(c4 + 0, r)] = f2tf(f.x);
            As[asw(c4 + 1, r)] = f2tf(f.y);
            As[asw(c4 + 2, r)] = f2tf(f.z);
            As[asw(c4 + 3, r)] = f2tf(f.w);
        }
        // stage B: 32 k x 128 n
#pragma unroll
        for (int p = 0; p < 4; p++) {
            int idx = tid + p * 256;
            int r = idx >> 5, c4 = (idx & 31) * 4;
            float4 f = *(const float4*)(Bmat + (size_t)(k0 + r) * N + col0 + c4);
            uint4 u;
            u.x = f2tf(f.x); u.y = f2tf(f.y); u.z = f2tf(f.z); u.w = f2tf(f.w);
            *(uint4*)&Bs[r * GST + c4] = u;
        }
        __syncthreads();
#pragma unroll
        for (int ks = 0; ks < 4; ks++) {
            int kk = ks * 8;
            uint32_t a[4][4], b[4][2];
#pragma unroll
            for (int i = 0; i < 4; i++) {
                int m = wm * 64 + i * 16 + g;
                a[i][0] = As[asw(kk + tq,     m)];
                a[i][1] = As[asw(kk + tq,     m + 8)];
                a[i][2] = As[asw(kk + tq + 4, m)];
                a[i][3] = As[asw(kk + tq + 4, m + 8)];
            }
#pragma unroll
            for (int j = 0; j < 4; j++) {
                int n = wn * 32 + j * 8 + g;
                b[j][0] = Bs[(kk + tq) * GST + n];
                b[j][1] = Bs[(kk + tq + 4) * GST + n];
            }
#pragma unroll
            for (int i = 0; i < 4; i++)
#pragma unroll
                for (int j = 0; j < 4; j++) mma_tf32(acc[i][j], a[i], b[j], acc[i][j]);
        }
        __syncthreads();
    }

    // epilogue: each thread owns (row, row+8) x (2 cols) per (i,j)
#pragma unroll
    for (int i = 0; i < 4; i++) {
        int rbase = row0 + wm * 64 + i * 16 + g;
#pragma unroll
        for (int j = 0; j < 4; j++) {
            int cbase = col0 + wn * 32 + j * 8 + 2 * tq;
#pragma unroll
            for (int h = 0; h < 2; h++) {
                int row = rbase + 8 * h;
                float2 f;
                f.x = acc[i][j][2 * h + 0] + bias[cbase + 0];
                f.y = acc[i][j][2 * h + 1] + bias[cbase + 1];
                if (mode) {
                    *(float2*)(outC + (size_t)row * N + cbase) = f;
                } else {
                    int part = cbase >> 10;
                    float* dst = (part == 0) ? g_q : (part == 1) ? g_k : g_v;
                    int wd = cbase & 1023;
                    int head = wd >> 6, hd = wd & 63;
                    int b = row >> 11, s = row & 2047;
                    size_t di = ((((size_t)b * NH + head) * S_LEN) + s) * HD + hd;
                    *(float2*)(dst + di) = f;
                }
            }
        }
    }
}

// ================= 3) per-head LayerNorm (scale only) + RoPE, in place ======
__global__ __launch_bounds__(256) void lnrope_kernel(const float* __restrict__ q_scale,
                                                     const float* __restrict__ k_scale) {
    int gw   = (blockIdx.x * 256 + threadIdx.x) >> 5;
    int lane = threadIdx.x & 31;
    int sel  = gw >> 16;                                 // 0=q, 1=k
    int idx  = gw & 65535;                               // (b*H+h)*S + s
    float* p = (sel ? g_k : g_q) + (size_t)idx * 64;
    const float* sc = sel ? k_scale : q_scale;
    int s = idx & 2047;

    float x0 = p[lane], x1 = p[lane + 32];
    float sum = x0 + x1;
#pragma unroll
    for (int off = 16; off; off >>= 1) sum += __shfl_xor_sync(0xffffffffu, sum, off);
    float mu = sum * (1.f / 64.f);
    float d0 = x0 - mu, d1 = x1 - mu;
    float vs = d0 * d0 + d1 * d1;
#pragma unroll
    for (int off = 16; off; off >>= 1) vs += __shfl_xor_sync(0xffffffffu, vs, off);
    float rstd = rsqrtf(vs * (1.f / 64.f) + 1e-6f);
    float y0 = d0 * rstd * sc[lane];
    float y1 = d1 * rstd * sc[lane + 32];

    float inv = expf((float)lane * NEG_LOG_BASE_OVER_32);
    float ang = (float)s * inv;
    float c, sn;
    sincosf(ang, &sn, &c);
    p[lane]      = y0 * c - y1 * sn;
    p[lane + 32] = y1 * c + y0 * sn;
}

// ======================= 4) flash attention, tf32 MMA ========================
// CTA = 128 queries, loop over 32 key-tiles of 64. 4 warps, each 32 q x 64 key.
// Smem (dynamic, tf32 words, stride 68):
//   Qs[128][68] | KPs[128][68] (K tile 64 rows, then reused for P 128 rows) | Vs[64][68]
#define AST 68
#define SM_Q  0
#define SM_KP (128 * AST)
#define SM_V  (256 * AST)
#define SMEM_ATTN_BYTES ((256 * AST + 64 * AST) * 4)

__global__ __launch_bounds__(128) void attn_tc() {
    extern __shared__ uint32_t smw[];
    uint32_t* Qs  = smw + SM_Q;
    uint32_t* KPs = smw + SM_KP;
    uint32_t* Vs  = smw + SM_V;

    int tid = threadIdx.x, lane = tid & 31, w = tid >> 5;
    int g = lane >> 2, tq = lane & 3;
    int bh = blockIdx.y, qt = blockIdx.x;
    const float* qb = g_q + ((size_t)bh * S_LEN + qt * 128) * HD;
    const float* kb = g_k + (size_t)bh * S_LEN * HD;
    const float* vb = g_v + (size_t)bh * S_LEN * HD;
    int mbase = w * 32;

    // stage Q (128x64), pre-scaled by 1/8 (exact power of two)
#pragma unroll
    for (int p = 0; p < 16; p++) {
        int idx = tid + p * 128;
        int r = idx >> 4, c4 = (idx & 15) * 4;
        float4 f = *(const float4*)(qb + r * 64 + c4);
        uint4 u;
        u.x = f2tf(f.x * 0.125f); u.y = f2tf(f.y * 0.125f);
        u.z = f2tf(f.z * 0.125f); u.w = f2tf(f.w * 0.125f);
        *(uint4*)&Qs[r * AST + c4] = u;
    }

    float o[2][8][4], mr[2][2], lr[2][2];
#pragma unroll
    for (int i = 0; i < 2; i++) {
        mr[i][0] = mr[i][1] = -1e30f;
        lr[i][0] = lr[i][1] = 0.f;
#pragma unroll
        for (int j = 0; j < 8; j++)
#pragma unroll
            for (int r = 0; r < 4; r++) o[i][j][r] = 0.f;
    }

    for (int kt = 0; kt < S_LEN / 64; kt++) {
        __syncthreads();   // Q ready (iter0); P/V reads of prev iter done
        const float* kbt = kb + kt * 64 * 64;
        const float* vbt = vb + kt * 64 * 64;
#pragma unroll
        for (int p = 0; p < 8; p++) {
            int idx = tid + p * 128;
            int r = idx >> 4, c4 = (idx & 15) * 4;
            float4 fk = *(const float4*)(kbt + r * 64 + c4);
            uint4 uk;
            uk.x = f2tf(fk.x); uk.y = f2tf(fk.y); uk.z = f2tf(fk.z); uk.w = f2tf(fk.w);
            *(uint4*)&KPs[r * AST + c4] = uk;
            float4 fv = *(const float4*)(vbt + r * 64 + c4);
            uint4 uv;
            uv.x = f2tf(fv.x); uv.y = f2tf(fv.y); uv.z = f2tf(fv.z); uv.w = f2tf(fv.w);
            *(uint4*)&Vs[r * AST + c4] = uv;
        }
        __syncthreads();

        // S = Q @ K^T  (contraction over hd=64)
        float s[2][8][4];
#pragma unroll
        for (int i = 0; i < 2; i++)
#pragma unroll
            for (int j = 0; j < 8; j++)
#pragma unroll
                for (int r = 0; r < 4; r++) s[i][j][r] = 0.f;
#pragma unroll
        for (int ks = 0; ks < 8; ks++) {
            int kk = ks * 8;
            uint32_t a[2][4], b[8][2];
#pragma unroll
            for (int i = 0; i < 2; i++) {
                int m = mbase + i * 16 + g;
                a[i][0] = Qs[m * AST + kk + tq];
                a[i][1] = Qs[(m + 8) * AST + kk + tq];
                a[i][2] = Qs[m * AST + kk + tq + 4];
                a[i][3] = Qs[(m + 8) * AST + kk + tq + 4];
            }
#pragma unroll
            for (int j = 0; j < 8; j++) {
                int n = j * 8 + g;
                b[j][0] = KPs[n * AST + kk + tq];
                b[j][1] = KPs[n * AST + kk + tq + 4];
            }
#pragma unroll
            for (int i = 0; i < 2; i++)
#pragma unroll
                for (int j = 0; j < 8; j++) mma_tf32(s[i][j], a[i], b[j], s[i][j]);
        }
        __syncthreads();   // all K reads done before P overwrites KPs

        // online softmax; write P (tf32) into KPs
#pragma unroll
        for (int i = 0; i < 2; i++) {
#pragma unroll
            for (int h = 0; h < 2; h++) {
                float rm = -1e30f;
#pragma unroll
                for (int j = 0; j < 8; j++)
                    rm = fmaxf(rm, fmaxf(s[i][j][2 * h], s[i][j][2 * h + 1]));
                rm = fmaxf(rm, __shfl_xor_sync(0xffffffffu, rm, 1));
                rm = fmaxf(rm, __shfl_xor_sync(0xffffffffu, rm, 2));
                float mn = fmaxf(mr[i][h], rm);
                float alpha = __expf(mr[i][h] - mn);
                mr[i][h] = mn;
                int row = mbase + i * 16 + h * 8 + g;
                float rs = 0.f;
#pragma unroll
                for (int j = 0; j < 8; j++) {
                    float p0 = __expf(s[i][j][2 * h] - mn);
                    float p1 = __expf(s[i][j][2 * h + 1] - mn);
                    rs += p0 + p1;
                    uint2 u; u.x = f2tf(p0); u.y = f2tf(p1);
                    *(uint2*)&KPs[row * AST + j * 8 + 2 * tq] = u;
                }
                rs += __shfl_xor_sync(0xffffffffu, rs, 1);
                rs += __shfl_xor_sync(0xffffffffu, rs, 2);
                lr[i][h] = lr[i][h] * alpha + rs;
#pragma unroll
                for (int j = 0; j < 8; j++) {
                    o[i][j][2 * h]     *= alpha;
                    o[i][j][2 * h + 1] *= alpha;
                }
            }
        }
        __syncthreads();   // P visible to all warps

        // O += P @ V  (contraction over key=64)
#pragma unroll
        for (int ks = 0; ks < 8; ks++) {
            int kk = ks * 8;
            uint32_t a[2][4], b[8][2];
#pragma unroll
            for (int i = 0; i < 2; i++) {
                int m = mbase + i * 16 + g;
                a[i][0] = KPs[m * AST + kk + tq];
                a[i][1] = KPs[(m + 8) * AST + kk + tq];
                a[i][2] = KPs[m * AST + kk + tq + 4];
                a[i][3] = KPs[(m + 8) * AST + kk + tq + 4];
            }
#pragma unroll
            for (int j = 0; j < 8; j++) {
                int n = j * 8 + g;
                b[j][0] = Vs[(kk + tq) * AST + n];
                b[j][1] = Vs[(kk + tq + 4) * AST + n];
            }
#pragma unroll
            for (int i = 0; i < 2; i++)
#pragma unroll
                for (int j = 0; j < 8; j++) mma_tf32(o[i][j], a[i], b[j], o[i][j]);
        }
    }

    // epilogue: divide by l, scatter to token-major [b,s,h,hd]
    int b = bh >> 4, h4 = bh & 15;
#pragma unroll
    for (int i = 0; i < 2; i++) {
#pragma unroll
        for (int h = 0; h < 2; h++) {
            float invl = 1.f / lr[i][h];
            int srow = qt * 128 + mbase + i * 16 + h * 8 + g;
#pragma unroll
            for (int j = 0; j < 8; j++) {
                float2 f;
                f.x = o[i][j][2 * h]     * invl;
                f.y = o[i][j][2 * h + 1] * invl;
                int col = j * 8 + 2 * tq;
                *(float2*)(g_attn + (((size_t)b * S_LEN + srow) * NH + h4) * HD + col) = f;
            }
        }
    }
}

// =========================== launch ==========================================
extern "C" void kernel_launch(void* const* d_in, const int* in_sizes, int n_in,
                              void* d_out, int out_size) {
    const float* x        = (const float*)d_in[0];
    const float* w_qkv    = (const float*)d_in[1];
    const float* b_qkv    = (const float*)d_in[2];
    const float* w_out    = (const float*)d_in[3];
    const float* b_out    = (const float*)d_in[4];
    const float* ln_scale = (const float*)d_in[5];
    const float* ln_bias  = (const float*)d_in[6];
    const float* q_scale  = (const float*)d_in[7];
    const float* k_scale  = (const float*)d_in[8];
    float* out = (float*)d_out;

    cudaFuncSetAttribute(attn_tc, cudaFuncAttributeMaxDynamicSharedMemorySize,
                         SMEM_ATTN_BYTES);

    ln_kernel<<<NTOK, 256>>>(x, ln_scale, ln_bias);
    gemm_tc<<<dim3(3 * D_DIM / 128, NTOK / 128), 256>>>(w_qkv, b_qkv, nullptr, 0, 3 * D_DIM);
    lnrope_kernel<<<2 * NB * NH * S_LEN / 8, 256>>>(q_scale, k_scale);
    attn_tc<<<dim3(S_LEN / 128, NB * NH), 128, SMEM_ATTN_BYTES>>>();
    gemm_tc<<<dim3(D_DIM / 128, NTOK / 128), 256>>>(w_out, b_out, out, 1, D_DIM);
}